// round 1
// baseline (speedup 1.0000x reference)
#include <cuda_runtime.h>

#define TX   128     // output columns per block (= threads per block)
#define TYO  128     // output rows per block
#define WIN  11
#define HALO 5
#define IMG_H 512
#define IMG_W 512

#define C1F 1.0e-4f
#define C2F 9.0e-4f
#define EPSF 1.0e-8f

__device__ double g_ssim_acc;

__global__ void ssim_zero_kernel() { g_ssim_acc = 0.0; }

__global__ void __launch_bounds__(TX) ssim_main_kernel(
    const float* __restrict__ x,
    const float* __restrict__ y,
    const float* __restrict__ w)
{
    __shared__ float sg[WIN];
    __shared__ float sx[2][TX + WIN - 1];
    __shared__ float sy[2][TX + WIN - 1];
    __shared__ float swarp[TX / 32];

    const int tid = threadIdx.x;

    // Extract separable 1D Gaussian: row sums of w (rows sum to g[i] since sum(g)=1).
    if (tid < WIN) {
        float s = 0.f;
        #pragma unroll
        for (int j = 0; j < WIN; ++j) s += __ldg(w + tid * WIN + j);
        sg[tid] = s;
    }
    __syncthreads();

    float rg[WIN];
    #pragma unroll
    for (int k = 0; k < WIN; ++k) rg[k] = sg[k];

    const int c0 = blockIdx.x * TX;
    const int r0 = blockIdx.y * TYO;
    const long img_off = (long)blockIdx.z * (IMG_H * IMG_W);
    const float* xi = x + img_off;
    const float* yi = y + img_off;

    // Accumulator queue: slot s holds the partial vertical conv for output
    // row r = ir + s - HALO (ir = current input row). Slot 0 completes each step.
    float aX[WIN], aY[WIN], aXX[WIN], aYY[WIN], aXY[WIN];
    #pragma unroll
    for (int s = 0; s < WIN; ++s) { aX[s]=0.f; aY[s]=0.f; aXX[s]=0.f; aYY[s]=0.f; aXY[s]=0.f; }

    float lsum = 0.f;

    for (int j = 0; j < TYO + WIN - 1; ++j) {
        const int ir = r0 - HALO + j;   // input row (uniform across block)
        const int b  = j & 1;

        if (ir >= 0 && ir < IMG_H) {
            const float* xr = xi + (long)ir * IMG_W;
            const float* yr = yi + (long)ir * IMG_W;

            // Stage row [c0-5, c0+TX+5) with zero padding at image edges.
            {
                int p  = tid;
                int cg = c0 - HALO + p;
                bool ok = (cg >= 0) && (cg < IMG_W);
                sx[b][p] = ok ? __ldg(xr + cg) : 0.f;
                sy[b][p] = ok ? __ldg(yr + cg) : 0.f;
            }
            if (tid < WIN - 1) {
                int p  = tid + TX;
                int cg = c0 - HALO + p;
                bool ok = (cg < IMG_W);           // cg >= 0 always here
                sx[b][p] = ok ? __ldg(xr + cg) : 0.f;
                sy[b][p] = ok ? __ldg(yr + cg) : 0.f;
            }
            __syncthreads();

            // Horizontal conv of the 5 planes (products computed on the fly).
            float hx = 0.f, hy = 0.f, hxx = 0.f, hyy = 0.f, hxy = 0.f;
            #pragma unroll
            for (int k = 0; k < WIN; ++k) {
                float xv = sx[b][tid + k];
                float yv = sy[b][tid + k];
                float gk = rg[k];
                float gx = gk * xv;
                float gy = gk * yv;
                hx  += gx;
                hy  += gy;
                hxx = fmaf(gx, xv, hxx);
                hxy = fmaf(gx, yv, hxy);
                hyy = fmaf(gy, yv, hyy);
            }

            // Scatter into the vertical accumulator queue.
            #pragma unroll
            for (int s = 0; s < WIN; ++s) {
                float wv = rg[WIN - 1 - s];
                aX[s]  = fmaf(wv, hx,  aX[s]);
                aY[s]  = fmaf(wv, hy,  aY[s]);
                aXX[s] = fmaf(wv, hxx, aXX[s]);
                aYY[s] = fmaf(wv, hyy, aYY[s]);
                aXY[s] = fmaf(wv, hxy, aXY[s]);
            }
        }
        // else: fully out-of-bounds row contributes zeros -> nothing to do.

        // Emit output row r = ir - HALO once its window is complete.
        if (j >= WIN - 1) {
            float mu_x = aX[0], mu_y = aY[0];
            float mu_x2 = mu_x * mu_x;
            float mu_y2 = mu_y * mu_y;
            float mu_xy = mu_x * mu_y;
            float sig_x2 = aXX[0] - mu_x2;
            float sig_y2 = aYY[0] - mu_y2;
            float sig_xy = aXY[0] - mu_xy;
            float num = (2.f * mu_xy + C1F) * (2.f * sig_xy + C2F);
            float den = (mu_x2 + mu_y2 + C1F) * (sig_x2 + sig_y2 + C2F) + EPSF;
            float v = __fdividef(num, den);
            v = fminf(fmaxf(v, 0.f), 1.f);
            lsum += v;
        }

        // Shift the queue.
        #pragma unroll
        for (int s = 0; s < WIN - 1; ++s) {
            aX[s]  = aX[s + 1];
            aY[s]  = aY[s + 1];
            aXX[s] = aXX[s + 1];
            aYY[s] = aYY[s + 1];
            aXY[s] = aXY[s + 1];
        }
        aX[WIN-1] = 0.f; aY[WIN-1] = 0.f; aXX[WIN-1] = 0.f; aYY[WIN-1] = 0.f; aXY[WIN-1] = 0.f;
    }

    // Block reduction.
    #pragma unroll
    for (int o = 16; o > 0; o >>= 1)
        lsum += __shfl_down_sync(0xFFFFFFFFu, lsum, o);
    if ((tid & 31) == 0) swarp[tid >> 5] = lsum;
    __syncthreads();
    if (tid == 0) {
        float s = 0.f;
        #pragma unroll
        for (int i = 0; i < TX / 32; ++i) s += swarp[i];
        atomicAdd(&g_ssim_acc, (double)s);
    }
}

__global__ void ssim_finalize_kernel(float* out, double inv_count) {
    out[0] = (float)(g_ssim_acc * inv_count);
}

extern "C" void kernel_launch(void* const* d_in, const int* in_sizes, int n_in,
                              void* d_out, int out_size) {
    const float* x = (const float*)d_in[0];
    const float* y = (const float*)d_in[1];
    const float* w = (const float*)d_in[2];
    float* out = (float*)d_out;

    const long total = (long)in_sizes[0];                 // N*C*H*W
    const int nimg = (int)(total / (IMG_H * IMG_W));      // = N*C

    ssim_zero_kernel<<<1, 1>>>();
    dim3 grid(IMG_W / TX, IMG_H / TYO, nimg);
    ssim_main_kernel<<<grid, TX>>>(x, y, w);
    ssim_finalize_kernel<<<1, 1>>>(out, 1.0 / (double)total);
}

// round 3
// speedup vs baseline: 1.7009x; 1.7009x over previous
#include <cuda_runtime.h>

#define TX    128    // output columns per block (= threads per block)
#define TYO   64     // output rows per block
#define WIN   11
#define HALO  5
#define IMG_H 512
#define IMG_W 512
#define NSTEP 77     // TYO + WIN - 1 = 74, padded to 7*11

#define C1F  1.0e-4f
#define C2F  9.0e-4f
#define EPSF 1.0e-8f

__device__ double g_ssim_acc;

__global__ void ssim_zero_kernel() { g_ssim_acc = 0.0; }

__global__ void __launch_bounds__(TX) ssim_main_kernel(
    const float* __restrict__ x,
    const float* __restrict__ y,
    const float* __restrict__ w)
{
    __shared__ float sg[WIN];
    __shared__ float sx[2][TX + WIN - 1];
    __shared__ float sy[2][TX + WIN - 1];
    __shared__ float swarp[TX / 32];

    const int tid = threadIdx.x;

    // Separable 1D Gaussian: row sums of w (rows of g*g^T sum to g[i] since sum(g)=1).
    if (tid < WIN) {
        float s = 0.f;
        #pragma unroll
        for (int j = 0; j < WIN; ++j) s += __ldg(w + tid * WIN + j);
        sg[tid] = s;
    }
    __syncthreads();

    float rg[WIN];
    #pragma unroll
    for (int k = 0; k < WIN; ++k) rg[k] = sg[k];

    const int c0 = blockIdx.x * TX;
    const int r0 = blockIdx.y * TYO;
    const long img_off = (long)blockIdx.z * (IMG_H * IMG_W);
    const float* xi = x + img_off;
    const float* yi = y + img_off;

    const int  cg_main = c0 - HALO + tid;
    const bool cg_main_ok = (cg_main >= 0) && (cg_main < IMG_W);
    const int  cg_tail = cg_main + TX;
    const bool cg_tail_ok = (tid < WIN - 1) && (cg_tail < IMG_W);

    // Rotated accumulator queue: physical slot (t+s)%11 holds logical slot s at step t.
    float aX[WIN], aY[WIN], aXX[WIN], aYY[WIN], aXY[WIN];
    #pragma unroll
    for (int s = 0; s < WIN; ++s) { aX[s]=0.f; aY[s]=0.f; aXX[s]=0.f; aYY[s]=0.f; aXY[s]=0.f; }

    float lsum = 0.f;
    int par = 0;

    // Prefetch row for step 0.
    float pfx, pfy, pfxt, pfyt;
    {
        const int ir = r0 - HALO;
        const bool rv = (ir >= 0);  // ir < IMG_H always at step 0
        const float* xr = xi + (long)ir * IMG_W;
        const float* yr = yi + (long)ir * IMG_W;
        pfx  = (rv && cg_main_ok) ? __ldg(xr + cg_main) : 0.f;
        pfy  = (rv && cg_main_ok) ? __ldg(yr + cg_main) : 0.f;
        pfxt = (rv && cg_tail_ok) ? __ldg(xr + cg_tail) : 0.f;
        pfyt = (rv && cg_tail_ok) ? __ldg(yr + cg_tail) : 0.f;
    }

    #define SSIM_STEP(JJ)                                                      \
    {                                                                          \
        const int t = tbase + (JJ);                                            \
        float* sxc = sx[par];                                                  \
        float* syc = sy[par];                                                  \
        /* Stage the prefetched row. */                                        \
        sxc[tid] = pfx;                                                        \
        syc[tid] = pfy;                                                        \
        if (tid < WIN - 1) { sxc[tid + TX] = pfxt; syc[tid + TX] = pfyt; }     \
        /* Prefetch next row (consumed next step -> latency hidden). */        \
        {                                                                      \
            const int irn = r0 - HALO + t + 1;                                 \
            const bool rv = (irn >= 0) && (irn < IMG_H);                       \
            const float* xr = xi + (long)irn * IMG_W;                          \
            const float* yr = yi + (long)irn * IMG_W;                          \
            pfx  = (rv && cg_main_ok) ? __ldg(xr + cg_main) : 0.f;             \
            pfy  = (rv && cg_main_ok) ? __ldg(yr + cg_main) : 0.f;             \
            pfxt = (rv && cg_tail_ok) ? __ldg(xr + cg_tail) : 0.f;             \
            pfyt = (rv && cg_tail_ok) ? __ldg(yr + cg_tail) : 0.f;             \
        }                                                                      \
        __syncthreads();                                                       \
        /* Horizontal conv of the 5 planes. */                                 \
        float hx = 0.f, hy = 0.f, hxx = 0.f, hyy = 0.f, hxy = 0.f;             \
        _Pragma("unroll")                                                      \
        for (int k = 0; k < WIN; ++k) {                                        \
            const float xv = sxc[tid + k];                                     \
            const float yv = syc[tid + k];                                     \
            const float gk = rg[k];                                            \
            const float gx = gk * xv;                                         \
            const float gy = gk * yv;                                         \
            hx += gx; hy += gy;                                                \
            hxx = fmaf(gx, xv, hxx);                                           \
            hxy = fmaf(gx, yv, hxy);                                           \
            hyy = fmaf(gy, yv, hyy);                                           \
        }                                                                      \
        /* Vertical scatter (compile-time rotated indices). */                 \
        _Pragma("unroll")                                                      \
        for (int s = 0; s < WIN; ++s) {                                        \
            const int q = ((JJ) + s) % WIN;                                    \
            const float wv = rg[WIN - 1 - s];                                  \
            aX[q]  = fmaf(wv, hx,  aX[q]);                                     \
            aY[q]  = fmaf(wv, hy,  aY[q]);                                     \
            aXX[q] = fmaf(wv, hxx, aXX[q]);                                    \
            aYY[q] = fmaf(wv, hyy, aYY[q]);                                    \
            aXY[q] = fmaf(wv, hxy, aXY[q]);                                    \
        }                                                                      \
        /* Emit completed output row (physical slot JJ), then recycle it. */   \
        if (t >= WIN - 1 && t < TYO + WIN - 1) {                               \
            const float mu_x = aX[(JJ)], mu_y = aY[(JJ)];                      \
            const float mu_x2 = mu_x * mu_x;                                   \
            const float mu_y2 = mu_y * mu_y;                                   \
            const float mu_xy = mu_x * mu_y;                                   \
            const float sig_x2 = aXX[(JJ)] - mu_x2;                            \
            const float sig_y2 = aYY[(JJ)] - mu_y2;                            \
            const float sig_xy = aXY[(JJ)] - mu_xy;                            \
            const float num = (2.f * mu_xy + C1F) * (2.f * sig_xy + C2F);      \
            const float den = (mu_x2 + mu_y2 + C1F) * (sig_x2 + sig_y2 + C2F) + EPSF; \
            float v = __fdividef(num, den);                                    \
            v = fminf(fmaxf(v, 0.f), 1.f);                                     \
            lsum += v;                                                         \
        }                                                                      \
        aX[(JJ)] = 0.f; aY[(JJ)] = 0.f;                                        \
        aXX[(JJ)] = 0.f; aYY[(JJ)] = 0.f; aXY[(JJ)] = 0.f;                     \
        par ^= 1;                                                              \
    }

    #pragma unroll 1
    for (int tbase = 0; tbase < NSTEP; tbase += WIN) {
        SSIM_STEP(0)  SSIM_STEP(1)  SSIM_STEP(2)  SSIM_STEP(3)
        SSIM_STEP(4)  SSIM_STEP(5)  SSIM_STEP(6)  SSIM_STEP(7)
        SSIM_STEP(8)  SSIM_STEP(9)  SSIM_STEP(10)
    }
    #undef SSIM_STEP

    // Block reduction.
    #pragma unroll
    for (int o = 16; o > 0; o >>= 1)
        lsum += __shfl_down_sync(0xFFFFFFFFu, lsum, o);
    if ((tid & 31) == 0) swarp[tid >> 5] = lsum;
    __syncthreads();
    if (tid == 0) {
        float s = 0.f;
        #pragma unroll
        for (int i = 0; i < TX / 32; ++i) s += swarp[i];
        atomicAdd(&g_ssim_acc, (double)s);
    }
}

__global__ void ssim_finalize_kernel(float* out, double inv_count) {
    out[0] = (float)(g_ssim_acc * inv_count);
}

extern "C" void kernel_launch(void* const* d_in, const int* in_sizes, int n_in,
                              void* d_out, int out_size) {
    const float* x = (const float*)d_in[0];
    const float* y = (const float*)d_in[1];
    const float* w = (const float*)d_in[2];
    float* out = (float*)d_out;

    const long total = (long)in_sizes[0];                 // N*C*H*W
    const int nimg = (int)(total / (IMG_H * IMG_W));      // = N*C

    ssim_zero_kernel<<<1, 1>>>();
    dim3 grid(IMG_W / TX, IMG_H / TYO, nimg);
    ssim_main_kernel<<<grid, TX>>>(x, y, w);
    ssim_finalize_kernel<<<1, 1>>>(out, 1.0 / (double)total);
}

// round 4
// speedup vs baseline: 1.7441x; 1.0254x over previous
#include <cuda_runtime.h>

#define TPB    64     // threads per block (2 warps)
#define CPT    2      // columns per thread (packed f32x2)
#define CBLK   128    // columns per block = TPB*CPT
#define TYO    64     // output rows per block
#define WIN    11
#define HALO   5
#define IMG_H  512
#define IMG_W  512
#define NSTEP  77     // 7*11 >= TYO+WIN-1 (=74)
#define STAGE  (CBLK + WIN - 1)   // 138
#define SPAD   144

#define C1F  1.0e-4f
#define C2F  9.0e-4f
#define EPSF 1.0e-8f

typedef unsigned long long u64;

__device__ double       g_ssim_acc;
__device__ unsigned int g_ssim_cnt;

__device__ __forceinline__ u64 pk2(float lo, float hi) {
    u64 r; asm("mov.b64 %0,{%1,%2};" : "=l"(r) : "f"(lo), "f"(hi)); return r;
}
__device__ __forceinline__ void upk2(u64 v, float& lo, float& hi) {
    asm("mov.b64 {%0,%1},%2;" : "=f"(lo), "=f"(hi) : "l"(v));
}
__device__ __forceinline__ u64 fma2(u64 a, u64 b, u64 c) {
    u64 d; asm("fma.rn.f32x2 %0,%1,%2,%3;" : "=l"(d) : "l"(a), "l"(b), "l"(c)); return d;
}
__device__ __forceinline__ u64 mul2(u64 a, u64 b) {
    u64 d; asm("mul.rn.f32x2 %0,%1,%2;" : "=l"(d) : "l"(a), "l"(b)); return d;
}
__device__ __forceinline__ u64 add2(u64 a, u64 b) {
    u64 d; asm("add.rn.f32x2 %0,%1,%2;" : "=l"(d) : "l"(a), "l"(b)); return d;
}
__device__ __forceinline__ u64 neg2(u64 a) { return a ^ 0x8000000080000000ull; }

__global__ void __launch_bounds__(TPB) ssim_main_kernel(
    const float* __restrict__ x,
    const float* __restrict__ y,
    const float* __restrict__ w,
    float* __restrict__ out,
    double inv_total)
{
    __shared__ float sg[WIN];
    __shared__ __align__(16) float sx[2][SPAD];
    __shared__ __align__(16) float sy[2][SPAD];
    __shared__ float swp[TPB / 32];

    const int tid = threadIdx.x;

    // Separable 1D Gaussian from the 2D window: row sums (rows of g g^T sum to g[i]).
    if (tid < WIN) {
        float s = 0.f;
        #pragma unroll
        for (int j = 0; j < WIN; ++j) s += __ldg(w + tid * WIN + j);
        sg[tid] = s;
    }
    __syncthreads();

    u64 g2[WIN];
    #pragma unroll
    for (int k = 0; k < WIN; ++k) { float gk = sg[k]; g2[k] = pk2(gk, gk); }

    const u64 C1P  = pk2(C1F, C1F);
    const u64 C2P  = pk2(C2F, C2F);
    const u64 EPSP = pk2(EPSF, EPSF);

    const int c0 = blockIdx.x * CBLK;
    const int r0 = blockIdx.y * TYO;
    const long img_off = (long)blockIdx.z * (IMG_H * IMG_W);
    const float* xi = x + img_off;
    const float* yi = y + img_off;

    // Staging slots this thread fills: p, p+64, (p+128 if tid<10). Global col = c0-5+p.
    const int  gc1 = c0 - HALO + tid;
    const int  gc2 = gc1 + TPB;
    const int  gc3 = gc1 + 2 * TPB;
    const bool ok1 = (gc1 >= 0) && (gc1 < IMG_W);
    const bool ok2 = (gc2 >= 0) && (gc2 < IMG_W);
    const bool ok3 = (tid < STAGE - 2 * TPB) && (gc3 < IMG_W);

    const int lc = CPT * tid;   // local staged read base: window = staged[lc .. lc+11]

    // Ring buffer: slot (t % 11) holds the 5 hconv planes for input row r0-5+t.
    u64 rX[WIN], rY[WIN], rXX[WIN], rYY[WIN], rXY[WIN];
    #pragma unroll
    for (int s = 0; s < WIN; ++s) { rX[s]=0; rY[s]=0; rXX[s]=0; rYY[s]=0; rXY[s]=0; }

    float lsum0 = 0.f, lsum1 = 0.f;
    int par = 0;

    // Prefetch row for step 0.
    float pxa, pxb, pxc, pya, pyb, pyc;
    {
        const int ir = r0 - HALO;
        const bool rv = (ir >= 0);
        const float* xr = xi + (long)ir * IMG_W;
        const float* yr = yi + (long)ir * IMG_W;
        pxa = (rv && ok1) ? __ldg(xr + gc1) : 0.f;
        pya = (rv && ok1) ? __ldg(yr + gc1) : 0.f;
        pxb = (rv && ok2) ? __ldg(xr + gc2) : 0.f;
        pyb = (rv && ok2) ? __ldg(yr + gc2) : 0.f;
        pxc = (rv && ok3) ? __ldg(xr + gc3) : 0.f;
        pyc = (rv && ok3) ? __ldg(yr + gc3) : 0.f;
    }

    // Vertical conv at emit: symmetric pairs, g[d] == g[10-d].
    #define VPLANE(RES, RNG, JJ)                                               \
    {                                                                          \
        u64 m_ = mul2(g2[5], RNG[((JJ) + 6) % WIN]);                           \
        m_ = fma2(g2[0], add2(RNG[((JJ) + 11) % WIN], RNG[((JJ) + 1) % WIN]), m_); \
        m_ = fma2(g2[1], add2(RNG[((JJ) + 10) % WIN], RNG[((JJ) + 2) % WIN]), m_); \
        m_ = fma2(g2[2], add2(RNG[((JJ) +  9) % WIN], RNG[((JJ) + 3) % WIN]), m_); \
        m_ = fma2(g2[3], add2(RNG[((JJ) +  8) % WIN], RNG[((JJ) + 4) % WIN]), m_); \
        m_ = fma2(g2[4], add2(RNG[((JJ) +  7) % WIN], RNG[((JJ) + 5) % WIN]), m_); \
        RES = m_;                                                              \
    }

    #define SSIM_STEP(JJ)                                                      \
    {                                                                          \
        const int t  = tbase + (JJ);                                           \
        const int ir = r0 - HALO + t;                                          \
        float* sxc = sx[par];                                                  \
        float* syc = sy[par];                                                  \
        /* Stage prefetched row. */                                            \
        sxc[tid] = pxa;            syc[tid] = pya;                             \
        sxc[tid + TPB] = pxb;      syc[tid + TPB] = pyb;                       \
        if (tid < STAGE - 2 * TPB) { sxc[tid + 2 * TPB] = pxc; syc[tid + 2 * TPB] = pyc; } \
        /* Prefetch next row (latency hidden behind barrier + compute). */     \
        {                                                                      \
            const int irn = ir + 1;                                            \
            const bool rv = (irn >= 0) && (irn < IMG_H);                       \
            const float* xr = xi + (long)irn * IMG_W;                          \
            const float* yr = yi + (long)irn * IMG_W;                          \
            pxa = (rv && ok1) ? __ldg(xr + gc1) : 0.f;                         \
            pya = (rv && ok1) ? __ldg(yr + gc1) : 0.f;                         \
            pxb = (rv && ok2) ? __ldg(xr + gc2) : 0.f;                         \
            pyb = (rv && ok2) ? __ldg(yr + gc2) : 0.f;                         \
            pxc = (rv && ok3) ? __ldg(xr + gc3) : 0.f;                         \
            pyc = (rv && ok3) ? __ldg(yr + gc3) : 0.f;                         \
        }                                                                      \
        __syncthreads();                                                       \
        if (ir >= 0 && ir < IMG_H && t < TYO + WIN - 1) {                      \
            /* Load 12 window values per plane (aligned 64-bit LDS). */        \
            float xv[WIN + 1], yv[WIN + 1];                                    \
            _Pragma("unroll")                                                  \
            for (int i = 0; i < 6; ++i) {                                      \
                float2 tx = *(const float2*)(sxc + lc + 2 * i);                \
                float2 ty = *(const float2*)(syc + lc + 2 * i);                \
                xv[2*i] = tx.x; xv[2*i+1] = tx.y;                              \
                yv[2*i] = ty.x; yv[2*i+1] = ty.y;                              \
            }                                                                  \
            /* Horizontal conv of 5 planes, 2 columns packed. */               \
            u64 pxk = pk2(xv[0], xv[1]);                                       \
            u64 pyk = pk2(yv[0], yv[1]);                                       \
            u64 gx = mul2(g2[0], pxk);                                         \
            u64 gy = mul2(g2[0], pyk);                                         \
            u64 hx = gx, hy = gy;                                              \
            u64 hxx = mul2(gx, pxk);                                           \
            u64 hxy = mul2(gx, pyk);                                           \
            u64 hyy = mul2(gy, pyk);                                           \
            _Pragma("unroll")                                                  \
            for (int k = 1; k < WIN; ++k) {                                    \
                pxk = pk2(xv[k], xv[k+1]);                                     \
                pyk = pk2(yv[k], yv[k+1]);                                     \
                gx = mul2(g2[k], pxk);                                         \
                gy = mul2(g2[k], pyk);                                         \
                hx = add2(hx, gx);                                             \
                hy = add2(hy, gy);                                             \
                hxx = fma2(gx, pxk, hxx);                                      \
                hxy = fma2(gx, pyk, hxy);                                      \
                hyy = fma2(gy, pyk, hyy);                                      \
            }                                                                  \
            rX[(JJ)] = hx; rY[(JJ)] = hy;                                      \
            rXX[(JJ)] = hxx; rYY[(JJ)] = hyy; rXY[(JJ)] = hxy;                 \
        } else {                                                               \
            rX[(JJ)] = 0; rY[(JJ)] = 0;                                        \
            rXX[(JJ)] = 0; rYY[(JJ)] = 0; rXY[(JJ)] = 0;                       \
        }                                                                      \
        /* Emit output row r = r0 + t - 10. */                                 \
        if (t >= WIN - 1 && t < TYO + WIN - 1) {                               \
            u64 mx, my, vxx, vyy, vxy;                                         \
            VPLANE(mx,  rX,  (JJ))                                             \
            VPLANE(my,  rY,  (JJ))                                             \
            VPLANE(vxx, rXX, (JJ))                                             \
            VPLANE(vyy, rYY, (JJ))                                             \
            VPLANE(vxy, rXY, (JJ))                                             \
            const u64 mu_x2 = mul2(mx, mx);                                    \
            const u64 mu_y2 = mul2(my, my);                                    \
            const u64 mu_xy = mul2(mx, my);                                    \
            const u64 pxy  = add2(mu_xy, mu_xy);      /* 2*mu_xy   */          \
            const u64 exy2 = add2(vxy, vxy);          /* 2*E[xy]   */          \
            const u64 A    = add2(mu_x2, mu_y2);                               \
            const u64 S    = add2(vxx, vyy);                                   \
            const u64 n1   = add2(pxy, C1P);                                   \
            const u64 n2   = add2(add2(exy2, C2P), neg2(pxy));                 \
            const u64 d1   = add2(A, C1P);                                     \
            const u64 d2   = add2(add2(S, C2P), neg2(A));                      \
            const u64 num  = mul2(n1, n2);                                     \
            const u64 den  = fma2(d1, d2, EPSP);                               \
            float n0, n1s, dd0, dd1;                                           \
            upk2(num, n0, n1s);                                                \
            upk2(den, dd0, dd1);                                               \
            float v0 = __fdividef(n0,  dd0);                                   \
            float v1 = __fdividef(n1s, dd1);                                   \
            v0 = fminf(fmaxf(v0, 0.f), 1.f);                                   \
            v1 = fminf(fmaxf(v1, 0.f), 1.f);                                   \
            lsum0 += v0;                                                       \
            lsum1 += v1;                                                       \
        }                                                                      \
        par ^= 1;                                                              \
    }

    #pragma unroll 1
    for (int tbase = 0; tbase < NSTEP; tbase += WIN) {
        SSIM_STEP(0)  SSIM_STEP(1)  SSIM_STEP(2)  SSIM_STEP(3)
        SSIM_STEP(4)  SSIM_STEP(5)  SSIM_STEP(6)  SSIM_STEP(7)
        SSIM_STEP(8)  SSIM_STEP(9)  SSIM_STEP(10)
    }
    #undef SSIM_STEP
    #undef VPLANE

    // Block reduction.
    float ls = lsum0 + lsum1;
    #pragma unroll
    for (int o = 16; o > 0; o >>= 1)
        ls += __shfl_down_sync(0xFFFFFFFFu, ls, o);
    if ((tid & 31) == 0) swp[tid >> 5] = ls;
    __syncthreads();

    if (tid == 0) {
        float bs = swp[0] + swp[1];
        atomicAdd(&g_ssim_acc, (double)bs);
        __threadfence();
        const unsigned nb = gridDim.x * gridDim.y * gridDim.z;
        const unsigned prev = atomicAdd(&g_ssim_cnt, 1u);
        if (prev == nb - 1u) {
            // Last block: finalize and reset for the next graph replay.
            double acc = atomicAdd(&g_ssim_acc, 0.0);
            out[0] = (float)(acc * inv_total);
            g_ssim_acc = 0.0;
            g_ssim_cnt = 0u;
            __threadfence();
        }
    }
}

extern "C" void kernel_launch(void* const* d_in, const int* in_sizes, int n_in,
                              void* d_out, int out_size) {
    const float* x = (const float*)d_in[0];
    const float* y = (const float*)d_in[1];
    const float* w = (const float*)d_in[2];
    float* out = (float*)d_out;

    const long total = (long)in_sizes[0];                 // N*C*H*W
    const int nimg = (int)(total / (IMG_H * IMG_W));      // = N*C

    dim3 grid(IMG_W / CBLK, IMG_H / TYO, nimg);
    ssim_main_kernel<<<grid, TPB>>>(x, y, w, out, 1.0 / (double)total);
}

// round 5
// speedup vs baseline: 2.0285x; 1.1631x over previous
#include <cuda_runtime.h>

#define TPB    64     // 2 warps; each warp owns 64 output columns
#define WPC    64     // columns per warp
#define CBLK   128    // columns per block
#define TYO    64     // output rows per block
#define WIN    11
#define HALO   5
#define IMG_H  512
#define IMG_W  512
#define NSTEP  77     // 7*11 >= TYO+WIN-1 (=74)
#define NPAIR  38     // staged pairs per warp row: cols [cw-6, cw+70)

#define C1F  1.0e-4f
#define C2F  9.0e-4f
#define EPSF 1.0e-8f

typedef unsigned long long u64;

__device__ double       g_ssim_acc;
__device__ unsigned int g_ssim_cnt;

__device__ __forceinline__ u64 pk2(float lo, float hi) {
    u64 r; asm("mov.b64 %0,{%1,%2};" : "=l"(r) : "f"(lo), "f"(hi)); return r;
}
__device__ __forceinline__ void upk2(u64 v, float& lo, float& hi) {
    asm("mov.b64 {%0,%1},%2;" : "=f"(lo), "=f"(hi) : "l"(v));
}
__device__ __forceinline__ u64 fma2(u64 a, u64 b, u64 c) {
    u64 d; asm("fma.rn.f32x2 %0,%1,%2,%3;" : "=l"(d) : "l"(a), "l"(b), "l"(c)); return d;
}
__device__ __forceinline__ u64 mul2(u64 a, u64 b) {
    u64 d; asm("mul.rn.f32x2 %0,%1,%2;" : "=l"(d) : "l"(a), "l"(b)); return d;
}
__device__ __forceinline__ u64 add2(u64 a, u64 b) {
    u64 d; asm("add.rn.f32x2 %0,%1,%2;" : "=l"(d) : "l"(a), "l"(b)); return d;
}
__device__ __forceinline__ u64 neg2(u64 a) { return a ^ 0x8000000080000000ull; }

__global__ void __launch_bounds__(TPB) ssim_main_kernel(
    const float* __restrict__ x,
    const float* __restrict__ y,
    const float* __restrict__ w,
    float* __restrict__ out,
    double inv_total)
{
    __shared__ float sg[WIN];
    __shared__ __align__(16) float4 sbuf[2][2][40];   // [warp][buf][pair], 2.5KB
    __shared__ float swp[TPB / 32];

    const int tid  = threadIdx.x;
    const int lane = tid & 31;
    const int wid  = tid >> 5;

    // Separable 1D Gaussian from the 2D window (rows of g g^T sum to g[i]).
    if (tid < WIN) {
        float s = 0.f;
        #pragma unroll
        for (int j = 0; j < WIN; ++j) s += __ldg(w + tid * WIN + j);
        sg[tid] = s;
    }
    __syncthreads();

    u64 g2[6];   // symmetric: tap k uses g2[k<=5 ? k : 10-k]
    #pragma unroll
    for (int d = 0; d < 6; ++d) { float gd = sg[d]; g2[d] = pk2(gd, gd); }

    const u64 C1P  = pk2(C1F, C1F);
    const u64 C2P  = pk2(C2F, C2F);
    const u64 EPSP = pk2(EPSF, EPSF);
    const u64 HLF  = pk2(0.5f, 0.5f);

    const int c0 = blockIdx.x * CBLK;
    const int r0 = blockIdx.y * TYO;
    const long img_off = (long)blockIdx.z * (IMG_H * IMG_W);
    const float* xi = x + img_off;
    const float* yi = y + img_off;

    const int cw = c0 + WPC * wid;       // this warp's first output column
    const int cb = cw - 6;               // staged base column (even)

    // Pairs this thread stages: p1 = lane, p2 = 32+lane (lane < 6).
    const int  col1 = cb + 2 * lane;
    const int  col2 = col1 + 64;
    const bool c1ok = (col1 >= 0) && (col1 < IMG_W);
    const bool c2ok = (lane < NPAIR - 32) && (col2 < IMG_W);

    // Ring: slot (t % 11) holds packed hconv planes of input row r0-5+t.
    u64 rP[WIN], rM[WIN], rPP[WIN], rMM[WIN];
    #pragma unroll
    for (int s = 0; s < WIN; ++s) { rP[s]=0; rM[s]=0; rPP[s]=0; rMM[s]=0; }

    float lsum0 = 0.f, lsum1 = 0.f;
    int par = 0;

    // Prefetch row for step 0 (ir = r0-5).
    float2 f1x, f1y, f2x, f2y;
    {
        const int ir = r0 - HALO;
        const bool rv = (ir >= 0);
        const float* xr = xi + (long)ir * IMG_W;
        const float* yr = yi + (long)ir * IMG_W;
        const float2 z = make_float2(0.f, 0.f);
        f1x = (rv && c1ok) ? __ldg((const float2*)(xr + col1)) : z;
        f1y = (rv && c1ok) ? __ldg((const float2*)(yr + col1)) : z;
        f2x = (rv && c2ok) ? __ldg((const float2*)(xr + col2)) : z;
        f2y = (rv && c2ok) ? __ldg((const float2*)(yr + col2)) : z;
    }

    // Vertical conv at emit: symmetric pairing, g[d] == g[10-d].
    #define VPLANE(RES, RNG, JJ)                                               \
    {                                                                          \
        u64 m_ = mul2(g2[5], RNG[((JJ) + 6) % WIN]);                           \
        m_ = fma2(g2[0], add2(RNG[((JJ) + 11) % WIN], RNG[((JJ) + 1) % WIN]), m_); \
        m_ = fma2(g2[1], add2(RNG[((JJ) + 10) % WIN], RNG[((JJ) + 2) % WIN]), m_); \
        m_ = fma2(g2[2], add2(RNG[((JJ) +  9) % WIN], RNG[((JJ) + 3) % WIN]), m_); \
        m_ = fma2(g2[3], add2(RNG[((JJ) +  8) % WIN], RNG[((JJ) + 4) % WIN]), m_); \
        m_ = fma2(g2[4], add2(RNG[((JJ) +  7) % WIN], RNG[((JJ) + 5) % WIN]), m_); \
        RES = m_;                                                              \
    }

    #define TAP(PP, PM, GK)                                                    \
    {                                                                          \
        const u64 gp_ = mul2(GK, PP);                                          \
        const u64 gm_ = mul2(GK, PM);                                          \
        hP  = add2(hP,  gp_);                                                  \
        hM  = add2(hM,  gm_);                                                  \
        hPP = fma2(gp_, PP, hPP);                                              \
        hMM = fma2(gm_, PM, hMM);                                              \
    }

    #define SSIM_STEP(JJ)                                                      \
    {                                                                          \
        const int t = tbase + (JJ);                                            \
        float4* buf = &sbuf[wid][par][0];                                      \
        /* Stage prefetched row as interleaved (p0,p1,m0,m1) pairs. */         \
        {                                                                      \
            float4 s1;                                                         \
            s1.x = f1x.x + f1y.x;  s1.y = f1x.y + f1y.y;                       \
            s1.z = f1x.x - f1y.x;  s1.w = f1x.y - f1y.y;                       \
            buf[lane] = s1;                                                    \
            if (lane < NPAIR - 32) {                                           \
                float4 s2;                                                     \
                s2.x = f2x.x + f2y.x;  s2.y = f2x.y + f2y.y;                   \
                s2.z = f2x.x - f2y.x;  s2.w = f2x.y - f2y.y;                   \
                buf[32 + lane] = s2;                                           \
            }                                                                  \
        }                                                                      \
        /* Prefetch next row. */                                               \
        {                                                                      \
            const int irn = r0 - HALO + t + 1;                                 \
            const bool rv = (irn >= 0) && (irn < IMG_H);                       \
            const float* xr = xi + (long)irn * IMG_W;                          \
            const float* yr = yi + (long)irn * IMG_W;                          \
            const float2 z = make_float2(0.f, 0.f);                            \
            f1x = (rv && c1ok) ? __ldg((const float2*)(xr + col1)) : z;        \
            f1y = (rv && c1ok) ? __ldg((const float2*)(yr + col1)) : z;        \
            f2x = (rv && c2ok) ? __ldg((const float2*)(xr + col2)) : z;        \
            f2y = (rv && c2ok) ? __ldg((const float2*)(yr + col2)) : z;        \
        }                                                                      \
        __syncwarp();                                                          \
        /* Window pairs: 7 LDS.128. f[j] = pairs lane..lane+6. */              \
        float4 f[7];                                                           \
        _Pragma("unroll")                                                      \
        for (int j = 0; j < 7; ++j) f[j] = buf[lane + j];                      \
        /* Horizontal conv: 11 taps over (p, m) and squares. */                \
        u64 hP, hM, hPP, hMM;                                                  \
        {   /* k = 0 (cross pack) */                                           \
            const u64 Pp = pk2(f[0].y, f[1].x);                                \
            const u64 Pm = pk2(f[0].w, f[1].z);                                \
            const u64 gp_ = mul2(g2[0], Pp);                                   \
            const u64 gm_ = mul2(g2[0], Pm);                                   \
            hP = gp_; hM = gm_;                                                \
            hPP = mul2(gp_, Pp);                                               \
            hMM = mul2(gm_, Pm);                                               \
        }                                                                      \
        { const u64 Pp = pk2(f[1].x, f[1].y), Pm = pk2(f[1].z, f[1].w); TAP(Pp, Pm, g2[1]) }  /* k=1  */ \
        { const u64 Pp = pk2(f[1].y, f[2].x), Pm = pk2(f[1].w, f[2].z); TAP(Pp, Pm, g2[2]) }  /* k=2  */ \
        { const u64 Pp = pk2(f[2].x, f[2].y), Pm = pk2(f[2].z, f[2].w); TAP(Pp, Pm, g2[3]) }  /* k=3  */ \
        { const u64 Pp = pk2(f[2].y, f[3].x), Pm = pk2(f[2].w, f[3].z); TAP(Pp, Pm, g2[4]) }  /* k=4  */ \
        { const u64 Pp = pk2(f[3].x, f[3].y), Pm = pk2(f[3].z, f[3].w); TAP(Pp, Pm, g2[5]) }  /* k=5  */ \
        { const u64 Pp = pk2(f[3].y, f[4].x), Pm = pk2(f[3].w, f[4].z); TAP(Pp, Pm, g2[4]) }  /* k=6  */ \
        { const u64 Pp = pk2(f[4].x, f[4].y), Pm = pk2(f[4].z, f[4].w); TAP(Pp, Pm, g2[3]) }  /* k=7  */ \
        { const u64 Pp = pk2(f[4].y, f[5].x), Pm = pk2(f[4].w, f[5].z); TAP(Pp, Pm, g2[2]) }  /* k=8  */ \
        { const u64 Pp = pk2(f[5].x, f[5].y), Pm = pk2(f[5].z, f[5].w); TAP(Pp, Pm, g2[1]) }  /* k=9  */ \
        { const u64 Pp = pk2(f[5].y, f[6].x), Pm = pk2(f[5].w, f[6].z); TAP(Pp, Pm, g2[0]) }  /* k=10 */ \
        rP[(JJ)] = hP;  rM[(JJ)] = hM;                                         \
        rPP[(JJ)] = hPP; rMM[(JJ)] = hMM;                                      \
        /* Emit output row r0 + t - 10. */                                     \
        if (t >= WIN - 1 && t < TYO + WIN - 1) {                               \
            u64 mp, mm, epp, emm;                                              \
            VPLANE(mp,  rP,  (JJ))                                             \
            VPLANE(mm,  rM,  (JJ))                                             \
            VPLANE(epp, rPP, (JJ))                                             \
            VPLANE(emm, rMM, (JJ))                                             \
            const u64 a   = mul2(mp, mp);                                      \
            const u64 b   = mul2(mm, mm);                                      \
            const u64 A    = mul2(HLF, add2(a, b));        /* mu_x^2+mu_y^2 */ \
            const u64 P2   = mul2(HLF, add2(a, neg2(b)));  /* 2*mu_x*mu_y  */  \
            const u64 S    = mul2(HLF, add2(epp, emm));    /* E[x^2]+E[y^2] */ \
            const u64 E2   = mul2(HLF, add2(epp, neg2(emm))); /* 2*E[xy]   */  \
            const u64 n1   = add2(P2, C1P);                                    \
            const u64 n2   = add2(add2(E2, C2P), neg2(P2));                    \
            const u64 d1   = add2(A, C1P);                                     \
            const u64 d2   = add2(add2(S, C2P), neg2(A));                      \
            const u64 num  = mul2(n1, n2);                                     \
            const u64 den  = fma2(d1, d2, EPSP);                               \
            float n0, n1s, dd0, dd1;                                           \
            upk2(num, n0, n1s);                                                \
            upk2(den, dd0, dd1);                                               \
            float v0 = __fdividef(n0,  dd0);                                   \
            float v1 = __fdividef(n1s, dd1);                                   \
            v0 = fminf(fmaxf(v0, 0.f), 1.f);                                   \
            v1 = fminf(fmaxf(v1, 0.f), 1.f);                                   \
            lsum0 += v0;                                                       \
            lsum1 += v1;                                                       \
        }                                                                      \
        par ^= 1;                                                              \
    }

    #pragma unroll 1
    for (int tbase = 0; tbase < NSTEP; tbase += WIN) {
        SSIM_STEP(0)  SSIM_STEP(1)  SSIM_STEP(2)  SSIM_STEP(3)
        SSIM_STEP(4)  SSIM_STEP(5)  SSIM_STEP(6)  SSIM_STEP(7)
        SSIM_STEP(8)  SSIM_STEP(9)  SSIM_STEP(10)
    }
    #undef SSIM_STEP
    #undef TAP
    #undef VPLANE

    // Block reduction.
    float ls = lsum0 + lsum1;
    #pragma unroll
    for (int o = 16; o > 0; o >>= 1)
        ls += __shfl_down_sync(0xFFFFFFFFu, ls, o);
    if (lane == 0) swp[wid] = ls;
    __syncthreads();

    if (tid == 0) {
        float bs = swp[0] + swp[1];
        atomicAdd(&g_ssim_acc, (double)bs);
        __threadfence();
        const unsigned nb = gridDim.x * gridDim.y * gridDim.z;
        const unsigned prev = atomicAdd(&g_ssim_cnt, 1u);
        if (prev == nb - 1u) {
            double acc = atomicAdd(&g_ssim_acc, 0.0);
            out[0] = (float)(acc * inv_total);
            g_ssim_acc = 0.0;
            g_ssim_cnt = 0u;
            __threadfence();
        }
    }
}

extern "C" void kernel_launch(void* const* d_in, const int* in_sizes, int n_in,
                              void* d_out, int out_size) {
    const float* x = (const float*)d_in[0];
    const float* y = (const float*)d_in[1];
    const float* w = (const float*)d_in[2];
    float* out = (float*)d_out;

    const long total = (long)in_sizes[0];                 // N*C*H*W
    const int nimg = (int)(total / (IMG_H * IMG_W));      // = N*C

    dim3 grid(IMG_W / CBLK, IMG_H / TYO, nimg);
    ssim_main_kernel<<<grid, TPB>>>(x, y, w, out, 1.0 / (double)total);
}

// round 6
// speedup vs baseline: 2.1098x; 1.0401x over previous
#include <cuda_runtime.h>

#define TPB    64     // 2 warps; each warp owns 64 output columns
#define WPC    64     // columns per warp
#define CBLK   128    // columns per block
#define TYO    32     // output rows per block
#define WIN    11
#define HALO   5
#define IMG_H  512
#define IMG_W  512
#define NSTEP  44     // 4*11 >= TYO+WIN-1 (=42)
#define NPAIR  38     // staged pairs per warp row: cols [cw-6, cw+70)

#define C1F  1.0e-4f
#define C2F  9.0e-4f
#define EPSF 1.0e-8f

typedef unsigned long long u64;

__device__ double       g_ssim_acc;
__device__ unsigned int g_ssim_cnt;

__device__ __forceinline__ u64 pk2(float lo, float hi) {
    u64 r; asm("mov.b64 %0,{%1,%2};" : "=l"(r) : "f"(lo), "f"(hi)); return r;
}
__device__ __forceinline__ void upk2(u64 v, float& lo, float& hi) {
    asm("mov.b64 {%0,%1},%2;" : "=f"(lo), "=f"(hi) : "l"(v));
}
__device__ __forceinline__ u64 fma2(u64 a, u64 b, u64 c) {
    u64 d; asm("fma.rn.f32x2 %0,%1,%2,%3;" : "=l"(d) : "l"(a), "l"(b), "l"(c)); return d;
}
__device__ __forceinline__ u64 mul2(u64 a, u64 b) {
    u64 d; asm("mul.rn.f32x2 %0,%1,%2;" : "=l"(d) : "l"(a), "l"(b)); return d;
}
__device__ __forceinline__ u64 add2(u64 a, u64 b) {
    u64 d; asm("add.rn.f32x2 %0,%1,%2;" : "=l"(d) : "l"(a), "l"(b)); return d;
}
__device__ __forceinline__ u64 neg2(u64 a) { return a ^ 0x8000000080000000ull; }

__global__ void __launch_bounds__(TPB, 8) ssim_main_kernel(
    const float* __restrict__ x,
    const float* __restrict__ y,
    const float* __restrict__ w,
    float* __restrict__ out,
    double inv_total)
{
    __shared__ float sg[WIN];
    __shared__ __align__(16) float4 sbuf[2][2][40];      // staging, 2.5KB
    __shared__ u64 ringPP[2][WIN][32];                   // 5.5KB
    __shared__ u64 ringMM[2][WIN][32];                   // 5.5KB
    __shared__ float swp[TPB / 32];

    const int tid  = threadIdx.x;
    const int lane = tid & 31;
    const int wid  = tid >> 5;

    // Separable 1D Gaussian from the 2D window (rows of g g^T sum to g[i]).
    if (tid < WIN) {
        float s = 0.f;
        #pragma unroll
        for (int j = 0; j < WIN; ++j) s += __ldg(w + tid * WIN + j);
        sg[tid] = s;
    }
    __syncthreads();

    u64 g2[6];   // symmetric: tap k uses g2[k<=5 ? k : 10-k]
    #pragma unroll
    for (int d = 0; d < 6; ++d) { float gd = sg[d]; g2[d] = pk2(gd, gd); }

    const u64 C1P  = pk2(C1F, C1F);
    const u64 C2P  = pk2(C2F, C2F);
    const u64 EPSP = pk2(EPSF, EPSF);
    const u64 HLF  = pk2(0.5f, 0.5f);

    const int c0 = blockIdx.x * CBLK;
    const int r0 = blockIdx.y * TYO;
    const long img_off = (long)blockIdx.z * (IMG_H * IMG_W);
    const float* xi = x + img_off;
    const float* yi = y + img_off;

    const int cw = c0 + WPC * wid;
    const int cb = cw - 6;

    const int  col1 = cb + 2 * lane;
    const int  col2 = col1 + 64;
    const bool c1ok = (col1 >= 0) && (col1 < IMG_W);
    const bool c2ok = (lane < NPAIR - 32) && (col2 < IMG_W);

    // rP/rM rings in registers; rPP/rMM rings in SMEM (slot (t % 11)).
    u64 rP[WIN], rM[WIN];
    #pragma unroll
    for (int s = 0; s < WIN; ++s) { rP[s]=0; rM[s]=0; }
    u64* myPP = &ringPP[wid][0][lane];   // stride between slots = 32 u64
    u64* myMM = &ringMM[wid][0][lane];
    #pragma unroll
    for (int s = 0; s < WIN; ++s) { myPP[s * 32] = 0; myMM[s * 32] = 0; }

    float lsum0 = 0.f, lsum1 = 0.f;
    int par = 0;

    // Prefetch row for step 0 (ir = r0-5).
    float2 f1x, f1y, f2x, f2y;
    {
        const int ir = r0 - HALO;
        const bool rv = (ir >= 0);
        const float* xr = xi + (long)ir * IMG_W;
        const float* yr = yi + (long)ir * IMG_W;
        const float2 z = make_float2(0.f, 0.f);
        f1x = (rv && c1ok) ? __ldg((const float2*)(xr + col1)) : z;
        f1y = (rv && c1ok) ? __ldg((const float2*)(yr + col1)) : z;
        f2x = (rv && c2ok) ? __ldg((const float2*)(xr + col2)) : z;
        f2y = (rv && c2ok) ? __ldg((const float2*)(yr + col2)) : z;
    }

    // Vertical conv over a register ring (symmetric pairing, g[d] == g[10-d]).
    #define VPLANE(RES, RNG, JJ)                                               \
    {                                                                          \
        u64 m_ = mul2(g2[5], RNG[((JJ) + 6) % WIN]);                           \
        m_ = fma2(g2[0], add2(RNG[((JJ) + 11) % WIN], RNG[((JJ) + 1) % WIN]), m_); \
        m_ = fma2(g2[1], add2(RNG[((JJ) + 10) % WIN], RNG[((JJ) + 2) % WIN]), m_); \
        m_ = fma2(g2[2], add2(RNG[((JJ) +  9) % WIN], RNG[((JJ) + 3) % WIN]), m_); \
        m_ = fma2(g2[3], add2(RNG[((JJ) +  8) % WIN], RNG[((JJ) + 4) % WIN]), m_); \
        m_ = fma2(g2[4], add2(RNG[((JJ) +  7) % WIN], RNG[((JJ) + 5) % WIN]), m_); \
        RES = m_;                                                              \
    }
    // Vertical conv over a SMEM ring (LDS.64 per slot).
    #define VPLANE_S(RES, BASE, JJ)                                            \
    {                                                                          \
        u64 m_ = mul2(g2[5], (BASE)[(((JJ) + 6) % WIN) * 32]);                 \
        m_ = fma2(g2[0], add2((BASE)[(((JJ) + 11) % WIN) * 32], (BASE)[(((JJ) + 1) % WIN) * 32]), m_); \
        m_ = fma2(g2[1], add2((BASE)[(((JJ) + 10) % WIN) * 32], (BASE)[(((JJ) + 2) % WIN) * 32]), m_); \
        m_ = fma2(g2[2], add2((BASE)[(((JJ) +  9) % WIN) * 32], (BASE)[(((JJ) + 3) % WIN) * 32]), m_); \
        m_ = fma2(g2[3], add2((BASE)[(((JJ) +  8) % WIN) * 32], (BASE)[(((JJ) + 4) % WIN) * 32]), m_); \
        m_ = fma2(g2[4], add2((BASE)[(((JJ) +  7) % WIN) * 32], (BASE)[(((JJ) + 5) % WIN) * 32]), m_); \
        RES = m_;                                                              \
    }

    #define TAP(PP, PM, GK)                                                    \
    {                                                                          \
        const u64 gp_ = mul2(GK, PP);                                          \
        const u64 gm_ = mul2(GK, PM);                                          \
        hP  = add2(hP,  gp_);                                                  \
        hM  = add2(hM,  gm_);                                                  \
        hPP = fma2(gp_, PP, hPP);                                              \
        hMM = fma2(gm_, PM, hMM);                                              \
    }

    #define SSIM_STEP(JJ)                                                      \
    if (tbase + (JJ) < TYO + WIN - 1) {                                        \
        const int t = tbase + (JJ);                                            \
        float4* buf = &sbuf[wid][par][0];                                      \
        /* Stage prefetched row as interleaved (p0,p1,m0,m1) pairs. */         \
        {                                                                      \
            float4 s1;                                                         \
            s1.x = f1x.x + f1y.x;  s1.y = f1x.y + f1y.y;                       \
            s1.z = f1x.x - f1y.x;  s1.w = f1x.y - f1y.y;                       \
            buf[lane] = s1;                                                    \
            if (lane < NPAIR - 32) {                                           \
                float4 s2;                                                     \
                s2.x = f2x.x + f2y.x;  s2.y = f2x.y + f2y.y;                   \
                s2.z = f2x.x - f2y.x;  s2.w = f2x.y - f2y.y;                   \
                buf[32 + lane] = s2;                                           \
            }                                                                  \
        }                                                                      \
        /* Prefetch next row. */                                               \
        {                                                                      \
            const int irn = r0 - HALO + t + 1;                                 \
            const bool rv = (irn >= 0) && (irn < IMG_H);                       \
            const float* xr = xi + (long)irn * IMG_W;                          \
            const float* yr = yi + (long)irn * IMG_W;                          \
            const float2 z = make_float2(0.f, 0.f);                            \
            f1x = (rv && c1ok) ? __ldg((const float2*)(xr + col1)) : z;        \
            f1y = (rv && c1ok) ? __ldg((const float2*)(yr + col1)) : z;        \
            f2x = (rv && c2ok) ? __ldg((const float2*)(xr + col2)) : z;        \
            f2y = (rv && c2ok) ? __ldg((const float2*)(yr + col2)) : z;        \
        }                                                                      \
        __syncwarp();                                                          \
        /* Window pairs: 7 LDS.128. */                                         \
        float4 f[7];                                                           \
        _Pragma("unroll")                                                      \
        for (int j = 0; j < 7; ++j) f[j] = buf[lane + j];                      \
        /* Horizontal conv: 11 taps over (p, m) and squares. */                \
        u64 hP, hM, hPP, hMM;                                                  \
        {   /* k = 0 (cross pack) */                                           \
            const u64 Pp = pk2(f[0].y, f[1].x);                                \
            const u64 Pm = pk2(f[0].w, f[1].z);                                \
            const u64 gp_ = mul2(g2[0], Pp);                                   \
            const u64 gm_ = mul2(g2[0], Pm);                                   \
            hP = gp_; hM = gm_;                                                \
            hPP = mul2(gp_, Pp);                                               \
            hMM = mul2(gm_, Pm);                                               \
        }                                                                      \
        { const u64 Pp = pk2(f[1].x, f[1].y), Pm = pk2(f[1].z, f[1].w); TAP(Pp, Pm, g2[1]) }  /* k=1  */ \
        { const u64 Pp = pk2(f[1].y, f[2].x), Pm = pk2(f[1].w, f[2].z); TAP(Pp, Pm, g2[2]) }  /* k=2  */ \
        { const u64 Pp = pk2(f[2].x, f[2].y), Pm = pk2(f[2].z, f[2].w); TAP(Pp, Pm, g2[3]) }  /* k=3  */ \
        { const u64 Pp = pk2(f[2].y, f[3].x), Pm = pk2(f[2].w, f[3].z); TAP(Pp, Pm, g2[4]) }  /* k=4  */ \
        { const u64 Pp = pk2(f[3].x, f[3].y), Pm = pk2(f[3].z, f[3].w); TAP(Pp, Pm, g2[5]) }  /* k=5  */ \
        { const u64 Pp = pk2(f[3].y, f[4].x), Pm = pk2(f[3].w, f[4].z); TAP(Pp, Pm, g2[4]) }  /* k=6  */ \
        { const u64 Pp = pk2(f[4].x, f[4].y), Pm = pk2(f[4].z, f[4].w); TAP(Pp, Pm, g2[3]) }  /* k=7  */ \
        { const u64 Pp = pk2(f[4].y, f[5].x), Pm = pk2(f[4].w, f[5].z); TAP(Pp, Pm, g2[2]) }  /* k=8  */ \
        { const u64 Pp = pk2(f[5].x, f[5].y), Pm = pk2(f[5].z, f[5].w); TAP(Pp, Pm, g2[1]) }  /* k=9  */ \
        { const u64 Pp = pk2(f[5].y, f[6].x), Pm = pk2(f[5].w, f[6].z); TAP(Pp, Pm, g2[0]) }  /* k=10 */ \
        rP[(JJ)] = hP;  rM[(JJ)] = hM;                                         \
        myPP[(JJ) * 32] = hPP;                                                 \
        myMM[(JJ) * 32] = hMM;                                                 \
        /* Emit output row r0 + t - 10. */                                     \
        if (t >= WIN - 1) {                                                    \
            u64 mp, mm, epp, emm;                                              \
            VPLANE(mp, rP, (JJ))                                               \
            VPLANE(mm, rM, (JJ))                                               \
            VPLANE_S(epp, myPP, (JJ))                                          \
            VPLANE_S(emm, myMM, (JJ))                                          \
            const u64 a   = mul2(mp, mp);                                      \
            const u64 b   = mul2(mm, mm);                                      \
            const u64 A    = mul2(HLF, add2(a, b));        /* mu_x^2+mu_y^2 */ \
            const u64 P2   = mul2(HLF, add2(a, neg2(b)));  /* 2*mu_x*mu_y  */  \
            const u64 S    = mul2(HLF, add2(epp, emm));    /* E[x^2]+E[y^2] */ \
            const u64 E2   = mul2(HLF, add2(epp, neg2(emm))); /* 2*E[xy]   */  \
            const u64 n1   = add2(P2, C1P);                                    \
            const u64 n2   = add2(add2(E2, C2P), neg2(P2));                    \
            const u64 d1   = add2(A, C1P);                                     \
            const u64 d2   = add2(add2(S, C2P), neg2(A));                      \
            const u64 num  = mul2(n1, n2);                                     \
            const u64 den  = fma2(d1, d2, EPSP);                               \
            float n0, n1s, dd0, dd1;                                           \
            upk2(num, n0, n1s);                                                \
            upk2(den, dd0, dd1);                                               \
            float v0 = __fdividef(n0,  dd0);                                   \
            float v1 = __fdividef(n1s, dd1);                                   \
            v0 = fminf(fmaxf(v0, 0.f), 1.f);                                   \
            v1 = fminf(fmaxf(v1, 0.f), 1.f);                                   \
            lsum0 += v0;                                                       \
            lsum1 += v1;                                                       \
        }                                                                      \
        par ^= 1;                                                              \
    }

    #pragma unroll 1
    for (int tbase = 0; tbase < NSTEP; tbase += WIN) {
        SSIM_STEP(0)  SSIM_STEP(1)  SSIM_STEP(2)  SSIM_STEP(3)
        SSIM_STEP(4)  SSIM_STEP(5)  SSIM_STEP(6)  SSIM_STEP(7)
        SSIM_STEP(8)  SSIM_STEP(9)  SSIM_STEP(10)
    }
    #undef SSIM_STEP
    #undef TAP
    #undef VPLANE
    #undef VPLANE_S

    // Block reduction.
    float ls = lsum0 + lsum1;
    #pragma unroll
    for (int o = 16; o > 0; o >>= 1)
        ls += __shfl_down_sync(0xFFFFFFFFu, ls, o);
    if (lane == 0) swp[wid] = ls;
    __syncthreads();

    if (tid == 0) {
        float bs = swp[0] + swp[1];
        atomicAdd(&g_ssim_acc, (double)bs);
        __threadfence();
        const unsigned nb = gridDim.x * gridDim.y * gridDim.z;
        const unsigned prev = atomicAdd(&g_ssim_cnt, 1u);
        if (prev == nb - 1u) {
            double acc = atomicAdd(&g_ssim_acc, 0.0);
            out[0] = (float)(acc * inv_total);
            g_ssim_acc = 0.0;
            g_ssim_cnt = 0u;
            __threadfence();
        }
    }
}

extern "C" void kernel_launch(void* const* d_in, const int* in_sizes, int n_in,
                              void* d_out, int out_size) {
    const float* x = (const float*)d_in[0];
    const float* y = (const float*)d_in[1];
    const float* w = (const float*)d_in[2];
    float* out = (float*)d_out;

    const long total = (long)in_sizes[0];                 // N*C*H*W
    const int nimg = (int)(total / (IMG_H * IMG_W));      // = N*C

    dim3 grid(IMG_W / CBLK, IMG_H / TYO, nimg);
    ssim_main_kernel<<<grid, TPB>>>(x, y, w, out, 1.0 / (double)total);
}